// round 1
// baseline (speedup 1.0000x reference)
#include <cuda_runtime.h>
#include <math.h>

#define BSZ      131072
#define ROWS     64
#define NTHREADS 256
#define KT       32
#define SA       257   // stride (floats) for 256-wide activation buffers
#define S3       65    // stride for 64-wide a3/w3 buffer
#define SW       257   // stride for staged weight tile rows

struct SmemLayout {
    float X[ROWS][4];
    float A1[ROWS * SA];
    float A2[ROWS * SA];
    float A3[ROWS * S3];
    float WT[KT * SW];
    float Grad[ROWS * 4];
    float Vv[ROWS];
    float Uu[ROWS];
};

// C[64][N] += A[64][K] * op(W).  Thread (rgrp,cgrp) owns rows rgrp*4..+3,
// cols cgrp+16*m.  Weights staged per 32-k tile into sWT[kk][n] (padded).
// TRANSW=false: W is [N][ldw], use W[n][k]   (forward: z = a @ W^T)
// TRANSW=true : W is [K][ldw], use W[k][n]   (backward: t = v @ W)
template <int MCNT, int N, int K, bool TRANSW>
__device__ __forceinline__ void gemm_acc(const float* __restrict__ W, int ldw,
                                         const float* __restrict__ sA, int lda,
                                         float* __restrict__ sWT,
                                         float (&acc)[4][MCNT], int tid) {
    const int rgrp = tid >> 4;
    const int cgrp = tid & 15;
    for (int k0 = 0; k0 < K; k0 += KT) {
        __syncthreads();
        #pragma unroll
        for (int idx = tid; idx < N * KT; idx += NTHREADS) {
            if (TRANSW) {
                int n  = idx % N;
                int kk = idx / N;
                sWT[kk * SW + n] = W[(k0 + kk) * ldw + n];
            } else {
                int kk = idx % KT;
                int n  = idx / KT;
                sWT[kk * SW + n] = W[n * ldw + k0 + kk];
            }
        }
        __syncthreads();
        #pragma unroll 4
        for (int kk = 0; kk < KT; kk++) {
            float a[4];
            #pragma unroll
            for (int i = 0; i < 4; i++)
                a[i] = sA[(rgrp * 4 + i) * lda + k0 + kk];
            #pragma unroll
            for (int m = 0; m < MCNT; m++) {
                float w = sWT[kk * SW + cgrp + 16 * m];
                #pragma unroll
                for (int i = 0; i < 4; i++)
                    acc[i][m] = fmaf(a[i], w, acc[i][m]);
            }
        }
    }
}

__global__ void __launch_bounds__(NTHREADS, 1)
clf_kernel(const float* __restrict__ x,
           const float* __restrict__ Vw1, const float* __restrict__ Vb1,
           const float* __restrict__ Vw2, const float* __restrict__ Vb2,
           const float* __restrict__ Vw3, const float* __restrict__ Vb3,
           const float* __restrict__ Uw1, const float* __restrict__ Ub1,
           const float* __restrict__ Uw2, const float* __restrict__ Ub2,
           const float* __restrict__ Uw3, const float* __restrict__ Ub3,
           float* __restrict__ out) {
    extern __shared__ char smem_raw[];
    SmemLayout& S = *reinterpret_cast<SmemLayout*>(smem_raw);
    const int tid  = threadIdx.x;
    const int rgrp = tid >> 4;
    const int cgrp = tid & 15;
    const int base = blockIdx.x * ROWS;

    // ---- load x tile (64 x 4) ----
    {
        int b = tid >> 2, j = tid & 3;   // 256 threads = 64*4 elements
        S.X[b][j] = x[(base + b) * 4 + j];
    }
    __syncthreads();

    // ---- a1 = tanh(x @ Vw1^T + Vb1); thread handles hidden unit h=tid ----
    {
        float w0 = Vw1[tid * 4 + 0], w1 = Vw1[tid * 4 + 1];
        float w2 = Vw1[tid * 4 + 2], w3 = Vw1[tid * 4 + 3];
        float bb = Vb1[tid];
        for (int b = 0; b < ROWS; b++) {
            float z = fmaf(S.X[b][0], w0, bb);
            z = fmaf(S.X[b][1], w1, z);
            z = fmaf(S.X[b][2], w2, z);
            z = fmaf(S.X[b][3], w3, z);
            S.A1[b * SA + tid] = tanhf(z);
        }
    }

    // ---- a2 = tanh(a1 @ Vw2^T + Vb2) ----
    {
        float acc[4][16];
        #pragma unroll
        for (int i = 0; i < 4; i++)
            #pragma unroll
            for (int m = 0; m < 16; m++) acc[i][m] = 0.f;
        gemm_acc<16, 256, 256, false>(Vw2, 256, S.A1, SA, S.WT, acc, tid);
        #pragma unroll
        for (int m = 0; m < 16; m++) {
            int n = cgrp + 16 * m;
            float bb = Vb2[n];
            #pragma unroll
            for (int i = 0; i < 4; i++)
                S.A2[(rgrp * 4 + i) * SA + n] = tanhf(acc[i][m] + bb);
        }
    }

    // ---- a3 = tanh(a2 @ Vw3^T + Vb3);  V = 0.5*sum(a3^2);  w3 = a3*(1-a3^2) ----
    {
        float acc[4][4];
        #pragma unroll
        for (int i = 0; i < 4; i++)
            #pragma unroll
            for (int m = 0; m < 4; m++) acc[i][m] = 0.f;
        gemm_acc<4, 64, 256, false>(Vw3, 256, S.A2, SA, S.WT, acc, tid);
        float pV[4] = {0.f, 0.f, 0.f, 0.f};
        #pragma unroll
        for (int m = 0; m < 4; m++) {
            int n = cgrp + 16 * m;
            float bb = Vb3[n];
            #pragma unroll
            for (int i = 0; i < 4; i++) {
                float a3 = tanhf(acc[i][m] + bb);
                pV[i] += a3 * a3;
                S.A3[(rgrp * 4 + i) * S3 + n] = a3 * (1.f - a3 * a3);
            }
        }
        #pragma unroll
        for (int i = 0; i < 4; i++) {
            float v = pV[i];
            v += __shfl_xor_sync(0xffffffffu, v, 8);
            v += __shfl_xor_sync(0xffffffffu, v, 4);
            v += __shfl_xor_sync(0xffffffffu, v, 2);
            v += __shfl_xor_sync(0xffffffffu, v, 1);
            if (cgrp == 0) S.Vv[rgrp * 4 + i] = 0.5f * v;
        }
    }

    // ---- t2' = (w3 @ Vw3) * (1 - a2^2), written in place into A2 ----
    {
        float acc[4][16];
        #pragma unroll
        for (int i = 0; i < 4; i++)
            #pragma unroll
            for (int m = 0; m < 16; m++) acc[i][m] = 0.f;
        gemm_acc<16, 256, 64, true>(Vw3, 256, S.A3, S3, S.WT, acc, tid);
        #pragma unroll
        for (int m = 0; m < 16; m++) {
            int n = cgrp + 16 * m;
            #pragma unroll
            for (int i = 0; i < 4; i++) {
                int off = (rgrp * 4 + i) * SA + n;
                float a2v = S.A2[off];
                S.A2[off] = acc[i][m] * (1.f - a2v * a2v);
            }
        }
    }

    // ---- t1' = (t2' @ Vw2) * (1 - a1^2);  grad_V = t1' @ Vw1 ----
    {
        float acc[4][16];
        #pragma unroll
        for (int i = 0; i < 4; i++)
            #pragma unroll
            for (int m = 0; m < 16; m++) acc[i][m] = 0.f;
        gemm_acc<16, 256, 256, true>(Vw2, 256, S.A2, SA, S.WT, acc, tid);
        float gp[4][4];
        #pragma unroll
        for (int i = 0; i < 4; i++)
            #pragma unroll
            for (int j = 0; j < 4; j++) gp[i][j] = 0.f;
        #pragma unroll
        for (int m = 0; m < 16; m++) {
            int n = cgrp + 16 * m;
            float vw0 = Vw1[n * 4 + 0], vw1 = Vw1[n * 4 + 1];
            float vw2 = Vw1[n * 4 + 2], vw3 = Vw1[n * 4 + 3];
            #pragma unroll
            for (int i = 0; i < 4; i++) {
                float a1v = S.A1[(rgrp * 4 + i) * SA + n];
                float t1 = acc[i][m] * (1.f - a1v * a1v);
                gp[i][0] = fmaf(t1, vw0, gp[i][0]);
                gp[i][1] = fmaf(t1, vw1, gp[i][1]);
                gp[i][2] = fmaf(t1, vw2, gp[i][2]);
                gp[i][3] = fmaf(t1, vw3, gp[i][3]);
            }
        }
        #pragma unroll
        for (int i = 0; i < 4; i++)
            #pragma unroll
            for (int j = 0; j < 4; j++) {
                float v = gp[i][j];
                v += __shfl_xor_sync(0xffffffffu, v, 8);
                v += __shfl_xor_sync(0xffffffffu, v, 4);
                v += __shfl_xor_sync(0xffffffffu, v, 2);
                v += __shfl_xor_sync(0xffffffffu, v, 1);
                if (cgrp == 0) S.Grad[(rgrp * 4 + i) * 4 + j] = v;
            }
    }
    __syncthreads();  // A1 reads done; safe to overwrite with u1

    // ---- u1 = tanh(x @ Uw1^T + Ub1), overwrite A1 ----
    {
        float w0 = Uw1[tid * 4 + 0], w1 = Uw1[tid * 4 + 1];
        float w2 = Uw1[tid * 4 + 2], w3 = Uw1[tid * 4 + 3];
        float bb = Ub1[tid];
        for (int b = 0; b < ROWS; b++) {
            float z = fmaf(S.X[b][0], w0, bb);
            z = fmaf(S.X[b][1], w1, z);
            z = fmaf(S.X[b][2], w2, z);
            z = fmaf(S.X[b][3], w3, z);
            S.A1[b * SA + tid] = tanhf(z);
        }
    }

    // ---- u2 = tanh(u1 @ Uw2^T + Ub2); fold dot with Uw3 ----
    {
        float acc[4][16];
        #pragma unroll
        for (int i = 0; i < 4; i++)
            #pragma unroll
            for (int m = 0; m < 16; m++) acc[i][m] = 0.f;
        gemm_acc<16, 256, 256, false>(Uw2, 256, S.A1, SA, S.WT, acc, tid);
        float pu[4] = {0.f, 0.f, 0.f, 0.f};
        #pragma unroll
        for (int m = 0; m < 16; m++) {
            int n = cgrp + 16 * m;
            float w = Uw3[n];
            float bb = Ub2[n];
            #pragma unroll
            for (int i = 0; i < 4; i++)
                pu[i] = fmaf(tanhf(acc[i][m] + bb), w, pu[i]);
        }
        #pragma unroll
        for (int i = 0; i < 4; i++) {
            float v = pu[i];
            v += __shfl_xor_sync(0xffffffffu, v, 8);
            v += __shfl_xor_sync(0xffffffffu, v, 4);
            v += __shfl_xor_sync(0xffffffffu, v, 2);
            v += __shfl_xor_sync(0xffffffffu, v, 1);
            if (cgrp == 0) S.Uu[rgrp * 4 + i] = v;
        }
    }
    __syncthreads();

    // ---- per-row epilogue: dynamics + Vdot + writes ----
    if (tid < ROWS) {
        int b = tid;
        float u = 20.f * tanhf(S.Uu[b] + Ub3[0]);
        float th = S.X[b][1], v = S.X[b][2], om = S.X[b][3];
        float s, c;
        sincosf(th, &s, &c);
        float den1 = c - 24.7f;
        float den2 = c * c - 24.7f;
        float f2 = (c * (9.8f * s + 11.5f * v) + 68.4f * v - 1.2f * om * om * s) / den1;
        float f3 = (-58.8f * v * c - 243.5f * v - s * (208.3f + om * om * c)) / den2;
        float g2 = (-1.8f * c - 10.9f) / den1;
        float g3 = (9.3f * c + 38.6f) / den2;
        float gv0 = S.Grad[b * 4 + 0], gv1 = S.Grad[b * 4 + 1];
        float gv2 = S.Grad[b * 4 + 2], gv3 = S.Grad[b * 4 + 3];
        float Lf = gv0 * v + gv1 * om + gv2 * f2 + gv3 * f3;
        float Lg = gv2 * g2 + gv3 * g3;
        int row = base + b;
        out[row]           = u;            // u  [BS,1]
        out[BSZ + row]     = S.Vv[b];      // V  [BS]
        out[2 * BSZ + row] = Lf + Lg * u;  // Vdot [BS,1,1]
    }
}

extern "C" void kernel_launch(void* const* d_in, const int* in_sizes, int n_in,
                              void* d_out, int out_size) {
    const float* x   = (const float*)d_in[0];
    const float* Vw1 = (const float*)d_in[1];
    const float* Vb1 = (const float*)d_in[2];
    const float* Vw2 = (const float*)d_in[3];
    const float* Vb2 = (const float*)d_in[4];
    const float* Vw3 = (const float*)d_in[5];
    const float* Vb3 = (const float*)d_in[6];
    const float* Uw1 = (const float*)d_in[7];
    const float* Ub1 = (const float*)d_in[8];
    const float* Uw2 = (const float*)d_in[9];
    const float* Ub2 = (const float*)d_in[10];
    const float* Uw3 = (const float*)d_in[11];
    const float* Ub3 = (const float*)d_in[12];
    float* out = (float*)d_out;

    cudaFuncSetAttribute(clf_kernel, cudaFuncAttributeMaxDynamicSharedMemorySize,
                         (int)sizeof(SmemLayout));
    clf_kernel<<<BSZ / ROWS, NTHREADS, sizeof(SmemLayout)>>>(
        x, Vw1, Vb1, Vw2, Vb2, Vw3, Vb3, Uw1, Ub1, Uw2, Ub2, Uw3, Ub3, out);
}

// round 2
// speedup vs baseline: 1.2753x; 1.2753x over previous
#include <cuda_runtime.h>
#include <math.h>

#define BSZ      131072
#define ROWS     64
#define NTHREADS 256
#define KT       64
#define SA       260   // stride (floats) for 256-wide activation buffers (div 4)
#define S3A      68    // stride for 64-wide a3/w3 buffer (div 4)
#define SW       258   // stride (floats) for staged weight tile rows (even, mod32=2)

struct SmemLayout {
    float X[ROWS][4];
    float A1[ROWS * SA];
    float A2[ROWS * SA];
    float A3[ROWS * S3A];
    float WT[KT * SW];
    float Grad[ROWS * 4];
    float Vv[ROWS];
    float Uu[ROWS];
};

typedef unsigned long long ull;

__device__ __forceinline__ ull dup2(float a) {
    ull r; unsigned int u = __float_as_uint(a);
    asm("mov.b64 %0, {%1, %1};" : "=l"(r) : "r"(u));
    return r;
}
__device__ __forceinline__ void unpack2(ull v, float& lo, float& hi) {
    unsigned int l, h;
    asm("mov.b64 {%0, %1}, %2;" : "=r"(l), "=r"(h) : "l"(v));
    lo = __uint_as_float(l); hi = __uint_as_float(h);
}
__device__ __forceinline__ void ffma2(ull& d, ull a, ull b) {
    asm("fma.rn.f32x2 %0, %1, %2, %0;" : "+l"(d) : "l"(a), "l"(b));
}

// C[64][N] += A[64][K] * op(W), packed 2 output columns per f32x2.
// Thread (rgrp = tid>>4, cgrp = tid&15) owns rows rgrp*4..+3 and column pairs
// n0 = 2*(cgrp + 16*m), n0+1 for m in [0, MP).
// TRANSW=false: W is [N][ldw], stage W[n][k]   (forward: z = a @ W^T)
// TRANSW=true : W is [K][ldw], stage W[k][n]   (backward: t = v @ W)
template <int MP, int N, int K, bool TRANSW>
__device__ __forceinline__ void gemm2(const float* __restrict__ W, int ldw,
                                      const float* __restrict__ sA, int lda,
                                      float* __restrict__ sWT,
                                      ull (&acc)[4][MP], int tid) {
    const int rgrp = tid >> 4;
    const int cgrp = tid & 15;
    for (int k0 = 0; k0 < K; k0 += KT) {
        __syncthreads();
        #pragma unroll
        for (int idx = tid; idx < N * KT; idx += NTHREADS) {
            if (TRANSW) {
                int n  = idx % N;           // consecutive tid -> consecutive n
                int kk = idx / N;
                sWT[kk * SW + n] = W[(k0 + kk) * ldw + n];
            } else {
                int kk = idx % KT;          // consecutive tid -> consecutive kk
                int n  = idx / KT;
                sWT[kk * SW + n] = W[n * ldw + k0 + kk];
            }
        }
        __syncthreads();
        #pragma unroll 2
        for (int kq = 0; kq < KT / 4; kq++) {
            float4 av[4];
            #pragma unroll
            for (int i = 0; i < 4; i++)
                av[i] = *reinterpret_cast<const float4*>(
                            &sA[(rgrp * 4 + i) * lda + k0 + kq * 4]);
            #pragma unroll
            for (int q = 0; q < 4; q++) {
                ull ad[4];
                #pragma unroll
                for (int i = 0; i < 4; i++) {
                    float a = (q == 0) ? av[i].x : (q == 1) ? av[i].y
                            : (q == 2) ? av[i].z : av[i].w;
                    ad[i] = dup2(a);
                }
                const float2* wrow =
                    reinterpret_cast<const float2*>(sWT + (kq * 4 + q) * SW);
                #pragma unroll
                for (int m = 0; m < MP; m++) {
                    ull w2 = *reinterpret_cast<const ull*>(&wrow[cgrp + 16 * m]);
                    #pragma unroll
                    for (int i = 0; i < 4; i++)
                        ffma2(acc[i][m], ad[i], w2);
                }
            }
        }
    }
}

template <int MP>
__device__ __forceinline__ void zero_acc(ull (&acc)[4][MP]) {
    #pragma unroll
    for (int i = 0; i < 4; i++)
        #pragma unroll
        for (int m = 0; m < MP; m++) acc[i][m] = 0ull;
}

__device__ __forceinline__ float redux16(float v) {
    v += __shfl_xor_sync(0xffffffffu, v, 8);
    v += __shfl_xor_sync(0xffffffffu, v, 4);
    v += __shfl_xor_sync(0xffffffffu, v, 2);
    v += __shfl_xor_sync(0xffffffffu, v, 1);
    return v;
}

__global__ void __launch_bounds__(NTHREADS, 1)
clf_kernel(const float* __restrict__ x,
           const float* __restrict__ Vw1, const float* __restrict__ Vb1,
           const float* __restrict__ Vw2, const float* __restrict__ Vb2,
           const float* __restrict__ Vw3, const float* __restrict__ Vb3,
           const float* __restrict__ Uw1, const float* __restrict__ Ub1,
           const float* __restrict__ Uw2, const float* __restrict__ Ub2,
           const float* __restrict__ Uw3, const float* __restrict__ Ub3,
           float* __restrict__ out) {
    extern __shared__ char smem_raw[];
    SmemLayout& S = *reinterpret_cast<SmemLayout*>(smem_raw);
    const int tid  = threadIdx.x;
    const int rgrp = tid >> 4;
    const int cgrp = tid & 15;
    const int base = blockIdx.x * ROWS;

    // ---- load x tile (64 x 4) ----
    {
        int b = tid >> 2, j = tid & 3;
        S.X[b][j] = x[(base + b) * 4 + j];
    }
    __syncthreads();

    // ---- a1 = tanh(x @ Vw1^T + Vb1); thread handles hidden unit h=tid ----
    {
        float4 w = *reinterpret_cast<const float4*>(&Vw1[tid * 4]);
        float bb = Vb1[tid];
        for (int b = 0; b < ROWS; b++) {
            float z = fmaf(S.X[b][0], w.x, bb);
            z = fmaf(S.X[b][1], w.y, z);
            z = fmaf(S.X[b][2], w.z, z);
            z = fmaf(S.X[b][3], w.w, z);
            S.A1[b * SA + tid] = tanhf(z);
        }
    }

    // ---- a2 = tanh(a1 @ Vw2^T + Vb2) ----
    {
        ull acc[4][8];
        zero_acc<8>(acc);
        gemm2<8, 256, 256, false>(Vw2, 256, S.A1, SA, S.WT, acc, tid);
        #pragma unroll
        for (int m = 0; m < 8; m++) {
            int n0 = 2 * (cgrp + 16 * m);
            float2 bb = *reinterpret_cast<const float2*>(&Vb2[n0]);
            #pragma unroll
            for (int i = 0; i < 4; i++) {
                float lo, hi; unpack2(acc[i][m], lo, hi);
                float2 r;
                r.x = tanhf(lo + bb.x);
                r.y = tanhf(hi + bb.y);
                *reinterpret_cast<float2*>(&S.A2[(rgrp * 4 + i) * SA + n0]) = r;
            }
        }
    }

    // ---- a3 = tanh(a2 @ Vw3^T + Vb3); V = 0.5*sum a3^2; A3 = a3*(1-a3^2) ----
    {
        ull acc[4][2];
        zero_acc<2>(acc);
        gemm2<2, 64, 256, false>(Vw3, 256, S.A2, SA, S.WT, acc, tid);
        float pV[4] = {0.f, 0.f, 0.f, 0.f};
        #pragma unroll
        for (int m = 0; m < 2; m++) {
            int n0 = 2 * (cgrp + 16 * m);
            float2 bb = *reinterpret_cast<const float2*>(&Vb3[n0]);
            #pragma unroll
            for (int i = 0; i < 4; i++) {
                float lo, hi; unpack2(acc[i][m], lo, hi);
                float a3x = tanhf(lo + bb.x);
                float a3y = tanhf(hi + bb.y);
                pV[i] += a3x * a3x + a3y * a3y;
                float2 r;
                r.x = a3x * (1.f - a3x * a3x);
                r.y = a3y * (1.f - a3y * a3y);
                *reinterpret_cast<float2*>(&S.A3[(rgrp * 4 + i) * S3A + n0]) = r;
            }
        }
        #pragma unroll
        for (int i = 0; i < 4; i++) {
            float v = redux16(pV[i]);
            if (cgrp == 0) S.Vv[rgrp * 4 + i] = 0.5f * v;
        }
    }

    // ---- t2' = (w3 @ Vw3) * (1 - a2^2), written in place into A2 ----
    {
        ull acc[4][8];
        zero_acc<8>(acc);
        gemm2<8, 256, 64, true>(Vw3, 256, S.A3, S3A, S.WT, acc, tid);
        #pragma unroll
        for (int m = 0; m < 8; m++) {
            int n0 = 2 * (cgrp + 16 * m);
            #pragma unroll
            for (int i = 0; i < 4; i++) {
                int off = (rgrp * 4 + i) * SA + n0;
                float2 a2v = *reinterpret_cast<const float2*>(&S.A2[off]);
                float lo, hi; unpack2(acc[i][m], lo, hi);
                float2 r;
                r.x = lo * (1.f - a2v.x * a2v.x);
                r.y = hi * (1.f - a2v.y * a2v.y);
                *reinterpret_cast<float2*>(&S.A2[off]) = r;
            }
        }
    }

    // ---- t1' = (t2' @ Vw2) * (1 - a1^2);  grad_V = t1' @ Vw1 ----
    {
        ull acc[4][8];
        zero_acc<8>(acc);
        gemm2<8, 256, 256, true>(Vw2, 256, S.A2, SA, S.WT, acc, tid);
        float gp[4][4];
        #pragma unroll
        for (int i = 0; i < 4; i++)
            #pragma unroll
            for (int j = 0; j < 4; j++) gp[i][j] = 0.f;
        #pragma unroll
        for (int m = 0; m < 8; m++) {
            int n0 = 2 * (cgrp + 16 * m);
            float4 wa = *reinterpret_cast<const float4*>(&Vw1[n0 * 4]);
            float4 wb = *reinterpret_cast<const float4*>(&Vw1[(n0 + 1) * 4]);
            #pragma unroll
            for (int i = 0; i < 4; i++) {
                float2 a1v = *reinterpret_cast<const float2*>(
                                 &S.A1[(rgrp * 4 + i) * SA + n0]);
                float lo, hi; unpack2(acc[i][m], lo, hi);
                float t1lo = lo * (1.f - a1v.x * a1v.x);
                float t1hi = hi * (1.f - a1v.y * a1v.y);
                gp[i][0] = fmaf(t1lo, wa.x, fmaf(t1hi, wb.x, gp[i][0]));
                gp[i][1] = fmaf(t1lo, wa.y, fmaf(t1hi, wb.y, gp[i][1]));
                gp[i][2] = fmaf(t1lo, wa.z, fmaf(t1hi, wb.z, gp[i][2]));
                gp[i][3] = fmaf(t1lo, wa.w, fmaf(t1hi, wb.w, gp[i][3]));
            }
        }
        #pragma unroll
        for (int i = 0; i < 4; i++)
            #pragma unroll
            for (int j = 0; j < 4; j++) {
                float v = redux16(gp[i][j]);
                if (cgrp == 0) S.Grad[(rgrp * 4 + i) * 4 + j] = v;
            }
    }
    __syncthreads();  // A1 reads done; safe to overwrite with u1

    // ---- u1 = tanh(x @ Uw1^T + Ub1), overwrite A1 ----
    {
        float4 w = *reinterpret_cast<const float4*>(&Uw1[tid * 4]);
        float bb = Ub1[tid];
        for (int b = 0; b < ROWS; b++) {
            float z = fmaf(S.X[b][0], w.x, bb);
            z = fmaf(S.X[b][1], w.y, z);
            z = fmaf(S.X[b][2], w.z, z);
            z = fmaf(S.X[b][3], w.w, z);
            S.A1[b * SA + tid] = tanhf(z);
        }
    }

    // ---- u2 = tanh(u1 @ Uw2^T + Ub2); fold dot with Uw3 ----
    {
        ull acc[4][8];
        zero_acc<8>(acc);
        gemm2<8, 256, 256, false>(Uw2, 256, S.A1, SA, S.WT, acc, tid);
        float pu[4] = {0.f, 0.f, 0.f, 0.f};
        #pragma unroll
        for (int m = 0; m < 8; m++) {
            int n0 = 2 * (cgrp + 16 * m);
            float2 uw = *reinterpret_cast<const float2*>(&Uw3[n0]);
            float2 bb = *reinterpret_cast<const float2*>(&Ub2[n0]);
            #pragma unroll
            for (int i = 0; i < 4; i++) {
                float lo, hi; unpack2(acc[i][m], lo, hi);
                pu[i] = fmaf(tanhf(lo + bb.x), uw.x, pu[i]);
                pu[i] = fmaf(tanhf(hi + bb.y), uw.y, pu[i]);
            }
        }
        #pragma unroll
        for (int i = 0; i < 4; i++) {
            float v = redux16(pu[i]);
            if (cgrp == 0) S.Uu[rgrp * 4 + i] = v;
        }
    }
    __syncthreads();

    // ---- per-row epilogue: dynamics + Vdot + writes ----
    if (tid < ROWS) {
        int b = tid;
        float u = 20.f * tanhf(S.Uu[b] + Ub3[0]);
        float th = S.X[b][1], v = S.X[b][2], om = S.X[b][3];
        float s, c;
        sincosf(th, &s, &c);
        float den1 = c - 24.7f;
        float den2 = c * c - 24.7f;
        float f2 = (c * (9.8f * s + 11.5f * v) + 68.4f * v - 1.2f * om * om * s) / den1;
        float f3 = (-58.8f * v * c - 243.5f * v - s * (208.3f + om * om * c)) / den2;
        float g2 = (-1.8f * c - 10.9f) / den1;
        float g3 = (9.3f * c + 38.6f) / den2;
        float gv0 = S.Grad[b * 4 + 0], gv1 = S.Grad[b * 4 + 1];
        float gv2 = S.Grad[b * 4 + 2], gv3 = S.Grad[b * 4 + 3];
        float Lf = gv0 * v + gv1 * om + gv2 * f2 + gv3 * f3;
        float Lg = gv2 * g2 + gv3 * g3;
        int row = base + b;
        out[row]           = u;            // u  [BS,1]
        out[BSZ + row]     = S.Vv[b];      // V  [BS]
        out[2 * BSZ + row] = Lf + Lg * u;  // Vdot [BS,1,1]
    }
}

extern "C" void kernel_launch(void* const* d_in, const int* in_sizes, int n_in,
                              void* d_out, int out_size) {
    const float* x   = (const float*)d_in[0];
    const float* Vw1 = (const float*)d_in[1];
    const float* Vb1 = (const float*)d_in[2];
    const float* Vw2 = (const float*)d_in[3];
    const float* Vb2 = (const float*)d_in[4];
    const float* Vw3 = (const float*)d_in[5];
    const float* Vb3 = (const float*)d_in[6];
    const float* Uw1 = (const float*)d_in[7];
    const float* Ub1 = (const float*)d_in[8];
    const float* Uw2 = (const float*)d_in[9];
    const float* Ub2 = (const float*)d_in[10];
    const float* Uw3 = (const float*)d_in[11];
    const float* Ub3 = (const float*)d_in[12];
    float* out = (float*)d_out;

    cudaFuncSetAttribute(clf_kernel, cudaFuncAttributeMaxDynamicSharedMemorySize,
                         (int)sizeof(SmemLayout));
    clf_kernel<<<BSZ / ROWS, NTHREADS, sizeof(SmemLayout)>>>(
        x, Vw1, Vb1, Vw2, Vb2, Vw3, Vb3, Uw1, Ub1, Uw2, Ub2, Uw3, Ub3, out);
}